// round 15
// baseline (speedup 1.0000x reference)
#include <cuda_runtime.h>
#include <cuda_bf16.h>
#include <math.h>
#include <cstdint>

#define T_LEN 1024
#define H_DIM 2048
#define NHEAD 32
#define HSZ   64

static const size_t TH = (size_t)T_LEN * H_DIM;

// ---------------- scratch layout (float units) ----------------
#define THF 2097152ull
#define OFS_XW   (0*THF)
#define OFS_XV   (1*THF)
#define OFS_XA   (2*THF)
#define OFS_XG   (3*THF)
#define OFS_R    (4*THF)
#define OFS_K    (5*THF)
#define OFS_V    (6*THF)
#define OFS_G    (7*THF)
#define OFS_A    (8*THF)
#define OFS_WD   (9*THF)
#define OFS_VM   (10*THF)
#define OFS_Y    (11*THF)
#define OFS_GT   (12*THF)
#define OFS_AT   (OFS_GT + 131072ull)
#define OFS_WT   (OFS_AT + 65536ull)
#define OFS_VT   (OFS_WT + 65536ull)
#define OFS_PART (OFS_VT + 32768ull)              // 8*1024*320 floats
#define OFS_S2M  (OFS_PART + 2621440ull)          // mid-scan state 32*64*64
#define OFS_BF16 (OFS_S2M + 131072ull)            // bf16 region (float units)
#define BO_WRH 0ull
#define BO_WRL 4194304ull
#define BO_WKH 8388608ull
#define BO_WKL 12582912ull
#define BO_WVH 16777216ull
#define BO_WVL 20971520ull
#define BO_WOH 25165824ull
#define BO_WOL 29360128ull
#define BO_XRH 33554432ull
#define BO_XRL 35651584ull
#define BO_XKH 37748736ull
#define BO_XKL 39845888ull
#define BO_XVH 41943040ull
#define BO_XVL 44040192ull
#define BO_OPH 46137344ull
#define BO_OPL 48234496ull
#define BF16_ELEMS 50331648ull
#define OFS_PK   (OFS_BF16 + BF16_ELEMS/2)        // packed scan ops
#define SCRATCH_FLOATS (OFS_PK + 12582912ull)

__device__ __align__(1024) float d_scratch[SCRATCH_FLOATS];

// ---------------- mma.sync helpers ----------------
__device__ __forceinline__ void ldmat4(uint32_t* r, uint32_t addr) {
    asm volatile("ldmatrix.sync.aligned.m8n8.x4.shared.b16 {%0,%1,%2,%3}, [%4];"
        : "=r"(r[0]), "=r"(r[1]), "=r"(r[2]), "=r"(r[3]) : "r"(addr));
}
__device__ __forceinline__ void mma16816(float* d, const uint32_t* a, const uint32_t* b) {
    asm volatile("mma.sync.aligned.m16n8k16.row.col.f32.bf16.bf16.f32 "
        "{%0,%1,%2,%3}, {%4,%5,%6,%7}, {%8,%9}, {%0,%1,%2,%3};"
        : "+f"(d[0]), "+f"(d[1]), "+f"(d[2]), "+f"(d[3])
        : "r"(a[0]), "r"(a[1]), "r"(a[2]), "r"(a[3]), "r"(b[0]), "r"(b[1]));
}

// ---------------- fp32 -> bf16 hi/lo split ----------------
__global__ void cvt_kernel(const float* __restrict__ x, __nv_bfloat16* __restrict__ hi,
                           __nv_bfloat16* __restrict__ lo)
{
    int i = blockIdx.x * blockDim.x + threadIdx.x;
    float4 v = ((const float4*)x)[i];
    float a[4] = {v.x, v.y, v.z, v.w};
    __nv_bfloat16 h[4], l[4];
    #pragma unroll
    for (int j = 0; j < 4; j++) {
        h[j] = __float2bfloat16(a[j]);
        l[j] = __float2bfloat16(a[j] - __bfloat162float(h[j]));
    }
    ((__nv_bfloat162*)hi)[2*i]   = __nv_bfloat162(h[0], h[1]);
    ((__nv_bfloat162*)hi)[2*i+1] = __nv_bfloat162(h[2], h[3]);
    ((__nv_bfloat162*)lo)[2*i]   = __nv_bfloat162(l[0], l[1]);
    ((__nv_bfloat162*)lo)[2*i+1] = __nv_bfloat162(l[2], l[3]);
}

__global__ void cvt3_kernel(const float* __restrict__ w0, const float* __restrict__ w1,
                            const float* __restrict__ w2, __nv_bfloat16* __restrict__ bfbase)
{
    int which = blockIdx.y;
    const float* x; __nv_bfloat16 *hi, *lo;
    if (which == 0)      { x = w0; hi = bfbase + BO_WRH; lo = bfbase + BO_WRL; }
    else if (which == 1) { x = w1; hi = bfbase + BO_WKH; lo = bfbase + BO_WKL; }
    else                 { x = w2; hi = bfbase + BO_WVH; lo = bfbase + BO_WVL; }
    int i = blockIdx.x * blockDim.x + threadIdx.x;
    float4 v = ((const float4*)x)[i];
    float a[4] = {v.x, v.y, v.z, v.w};
    __nv_bfloat16 h[4], l[4];
    #pragma unroll
    for (int j = 0; j < 4; j++) {
        h[j] = __float2bfloat16(a[j]);
        l[j] = __float2bfloat16(a[j] - __bfloat162float(h[j]));
    }
    ((__nv_bfloat162*)hi)[2*i]   = __nv_bfloat162(h[0], h[1]);
    ((__nv_bfloat162*)hi)[2*i+1] = __nv_bfloat162(h[2], h[3]);
    ((__nv_bfloat162*)lo)[2*i]   = __nv_bfloat162(l[0], l[1]);
    ((__nv_bfloat162*)lo)[2*i+1] = __nv_bfloat162(l[2], l[3]);
}

// ---------------- HMMA split-bf16 GEMM (2-stage, 147KB smem) ----------------
#define SROW 144
#define TILE_B (128*SROW)
#define S_ALO 18432
#define S_BHI 36864
#define S_BLO 55296
#define STAGE_B 73728
#define GEMM_SMEM (2*STAGE_B)

struct GemmArgs {
    const __nv_bfloat16 *Ah[3], *Al[3], *Bh[3], *Bl[3];
    float* C[3];
    const float* R[3];
    int m0;
};

__global__ void __launch_bounds__(256, 1)
mma_gemm_kernel(GemmArgs ga)
{
    extern __shared__ char smem[];
    const uint32_t sb = (uint32_t)__cvta_generic_to_shared(smem);
    const int tid = threadIdx.x;
    const int lane = tid & 31, wid = tid >> 5;
    const int wm = wid >> 2, wn = wid & 3;
    const int g = blockIdx.z;
    const int bm = ga.m0 + blockIdx.y * 128, bn = blockIdx.x * 128;
    const int lr = lane & 15, lc = lane >> 4;

    float acc[4][4][4];
    #pragma unroll
    for (int a = 0; a < 4; a++)
        #pragma unroll
        for (int b = 0; b < 4; b++)
            #pragma unroll
            for (int c = 0; c < 4; c++) acc[a][b][c] = 0.f;

    const __nv_bfloat16* gp[4];
    gp[0] = ga.Ah[g] + (size_t)bm * 2048;
    gp[1] = ga.Al[g] + (size_t)bm * 2048;
    gp[2] = ga.Bh[g] + (size_t)bn * 2048;
    gp[3] = ga.Bl[g] + (size_t)bn * 2048;

    auto issue = [&](int c) {
        uint32_t stage = sb + (uint32_t)(c & 1) * STAGE_B;
        const int kc = c * 64;
        #pragma unroll
        for (int t = 0; t < 4; t++) {
            #pragma unroll
            for (int i = 0; i < 4; i++) {
                int lin = tid + i * 256;
                int row = lin >> 3, seg = lin & 7;
                uint32_t s = stage + t * TILE_B + row * SROW + seg * 16;
                const __nv_bfloat16* gsrc = gp[t] + (size_t)row * 2048 + kc + seg * 8;
                asm volatile("cp.async.cg.shared.global [%0], [%1], 16;" :: "r"(s), "l"(gsrc));
            }
        }
        asm volatile("cp.async.commit_group;");
    };

    issue(0);
    for (int c = 0; c < 32; c++) {
        if (c < 31) {
            issue(c + 1);
            asm volatile("cp.async.wait_group 1;");
        } else {
            asm volatile("cp.async.wait_group 0;");
        }
        __syncthreads();
        uint32_t stage = sb + (uint32_t)(c & 1) * STAGE_B;
        #pragma unroll
        for (int ks = 0; ks < 4; ks++) {
            const int kb2 = (ks * 16 + lc * 8) * 2;
            uint32_t ah[4][4], al[4][4], bh[4][2], bl[4][2];
            #pragma unroll
            for (int mt = 0; mt < 4; mt++) {
                uint32_t ro = (uint32_t)((wm * 64 + mt * 16 + lr) * SROW + kb2);
                ldmat4(ah[mt], stage + ro);
                ldmat4(al[mt], stage + S_ALO + ro);
            }
            #pragma unroll
            for (int j = 0; j < 2; j++) {
                uint32_t ro = (uint32_t)((wn * 32 + j * 16 + lr) * SROW + kb2);
                uint32_t r[4];
                ldmat4(r, stage + S_BHI + ro);
                bh[2*j][0] = r[0]; bh[2*j][1] = r[2];
                bh[2*j+1][0] = r[1]; bh[2*j+1][1] = r[3];
                ldmat4(r, stage + S_BLO + ro);
                bl[2*j][0] = r[0]; bl[2*j][1] = r[2];
                bl[2*j+1][0] = r[1]; bl[2*j+1][1] = r[3];
            }
            #pragma unroll
            for (int mt = 0; mt < 4; mt++)
                #pragma unroll
                for (int nt = 0; nt < 4; nt++)
                    mma16816(acc[mt][nt], ah[mt], bh[nt]);
            #pragma unroll
            for (int mt = 0; mt < 4; mt++)
                #pragma unroll
                for (int nt = 0; nt < 4; nt++)
                    mma16816(acc[mt][nt], ah[mt], bl[nt]);
            #pragma unroll
            for (int mt = 0; mt < 4; mt++)
                #pragma unroll
                for (int nt = 0; nt < 4; nt++)
                    mma16816(acc[mt][nt], al[mt], bh[nt]);
        }
        __syncthreads();
    }

    float* C = ga.C[g];
    const float* R = ga.R[g];
    #pragma unroll
    for (int mt = 0; mt < 4; mt++) {
        int r0 = bm + wm * 64 + mt * 16 + (lane >> 2);
        #pragma unroll
        for (int nt = 0; nt < 4; nt++) {
            int col = bn + wn * 32 + nt * 8 + (lane & 3) * 2;
            float2 v0 = make_float2(acc[mt][nt][0], acc[mt][nt][1]);
            float2 v1 = make_float2(acc[mt][nt][2], acc[mt][nt][3]);
            if (R != nullptr) {
                float2 q0 = *(const float2*)(R + (size_t)r0 * 2048 + col);
                float2 q1 = *(const float2*)(R + (size_t)(r0 + 8) * 2048 + col);
                v0.x += q0.x; v0.y += q0.y; v1.x += q1.x; v1.y += q1.y;
            }
            *(float2*)(C + (size_t)r0 * 2048 + col) = v0;
            *(float2*)(C + (size_t)(r0 + 8) * 2048 + col) = v1;
        }
    }
}

// ---------------- fused stage-2 SGEMM ----------------
__global__ void s2_gemm_kernel(const float* __restrict__ gt, const float* __restrict__ at,
                               const float* __restrict__ wt, const float* __restrict__ vt,
                               const float* __restrict__ g2, const float* __restrict__ a2,
                               const float* __restrict__ w2, const float* __restrict__ v2,
                               const float* __restrict__ a0, const float* __restrict__ w0,
                               const float* __restrict__ v0,
                               float* __restrict__ G, float* __restrict__ A,
                               float* __restrict__ W, float* __restrict__ V, int zoff)
{
    __shared__ float As[16][68];
    __shared__ float Bs[16][68];
    const float* Ain; const float* Bin; const float* bias; float* Cout;
    int K, mode;
    switch (blockIdx.z + zoff) {
        case 0:  Ain = gt; Bin = g2; Cout = G; bias = nullptr; K = 128; mode = 0; break;
        case 1:  Ain = at; Bin = a2; Cout = A; bias = a0;      K = 64;  mode = 3; break;
        case 2:  Ain = wt; Bin = w2; Cout = W; bias = w0;      K = 64;  mode = 4; break;
        default: Ain = vt; Bin = v2; Cout = V; bias = v0;      K = 32;  mode = 3; break;
    }
    const int N = H_DIM;
    const int tid = threadIdx.x;
    const int tx = tid & 15, ty = tid >> 4;
    const int bm = blockIdx.y * 64, bn = blockIdx.x * 64;
    float acc[4][4] = {};
    for (int k0 = 0; k0 < K; k0 += 16) {
        {
            int r = tid >> 2, c = (tid & 3) << 2;
            #pragma unroll
            for (int u = 0; u < 4; u++) {
                int gc = k0 + c + u;
                As[c + u][r] = (gc < K) ? Ain[(size_t)(bm + r) * K + gc] : 0.f;
            }
        }
        {
            int kr = tid >> 4, nc = (tid & 15) << 2;
            int gk = k0 + kr;
            #pragma unroll
            for (int u = 0; u < 4; u++)
                Bs[kr][nc + u] = (gk < K) ? Bin[(size_t)gk * N + bn + nc + u] : 0.f;
        }
        __syncthreads();
        #pragma unroll
        for (int kk = 0; kk < 16; kk++) {
            const float4 a4 = *(const float4*)&As[kk][ty << 2];
            const float4 b4 = *(const float4*)&Bs[kk][tx << 2];
            float a[4] = {a4.x, a4.y, a4.z, a4.w};
            float b[4] = {b4.x, b4.y, b4.z, b4.w};
            #pragma unroll
            for (int i = 0; i < 4; i++)
                #pragma unroll
                for (int j = 0; j < 4; j++)
                    acc[i][j] = fmaf(a[i], b[j], acc[i][j]);
        }
        __syncthreads();
    }
    #pragma unroll
    for (int i = 0; i < 4; i++) {
        int m = bm + (ty << 2) + i;
        #pragma unroll
        for (int j = 0; j < 4; j++) {
            int n = bn + (tx << 2) + j;
            float v = acc[i][j];
            if (mode == 3)      v = 1.f / (1.f + expf(-(bias[n] + v)));
            else if (mode == 4) v = expf(-0.606531f / (1.f + expf(-(bias[n] + v))));
            Cout[(size_t)m * N + n] = v;
        }
    }
}

// ---------------- stage-1 split-K GEMM ----------------
__global__ void __launch_bounds__(256) s1_splitk_kernel(
    const float* __restrict__ xg, const float* __restrict__ xa,
    const float* __restrict__ xw, const float* __restrict__ xv,
    const float* __restrict__ g1, const float* __restrict__ a1,
    const float* __restrict__ w1, const float* __restrict__ v1,
    float* __restrict__ part)
{
    __shared__ float As[16][68];
    __shared__ float Bs[16][68];
    const int tid = threadIdx.x, tx = tid & 15, ty = tid >> 4;
    const int bx = blockIdx.x;
    const float* A; const float* B; int matN, bn, coff;
    if (bx == 0)      { A = xg; B = g1; matN = 128; bn = 0;  coff = 0; }
    else if (bx == 1) { A = xg; B = g1; matN = 128; bn = 64; coff = 64; }
    else if (bx == 2) { A = xa; B = a1; matN = 64;  bn = 0;  coff = 128; }
    else if (bx == 3) { A = xw; B = w1; matN = 64;  bn = 0;  coff = 192; }
    else              { A = xv; B = v1; matN = 32;  bn = 0;  coff = 256; }
    const int bm = blockIdx.y * 64;
    const int kb = blockIdx.z * 256;
    float acc[4][4] = {};
    for (int k0 = kb; k0 < kb + 256; k0 += 16) {
        {
            int r = tid >> 2, c = (tid & 3) << 2;
            #pragma unroll
            for (int u = 0; u < 4; u++)
                As[c + u][r] = A[(size_t)(bm + r) * H_DIM + k0 + c + u];
        }
        {
            int kr = tid >> 4, nc = (tid & 15) << 2;
            #pragma unroll
            for (int u = 0; u < 4; u++) {
                int n = bn + nc + u;
                Bs[kr][nc + u] = (n < matN) ? B[(size_t)(k0 + kr) * matN + n] : 0.f;
            }
        }
        __syncthreads();
        #pragma unroll
        for (int kk = 0; kk < 16; kk++) {
            const float4 a4 = *(const float4*)&As[kk][ty << 2];
            const float4 b4 = *(const float4*)&Bs[kk][tx << 2];
            float a[4] = {a4.x, a4.y, a4.z, a4.w};
            float b[4] = {b4.x, b4.y, b4.z, b4.w};
            #pragma unroll
            for (int i = 0; i < 4; i++)
                #pragma unroll
                for (int j = 0; j < 4; j++)
                    acc[i][j] = fmaf(a[i], b[j], acc[i][j]);
        }
        __syncthreads();
    }
    float* prow = part + (size_t)blockIdx.z * 1024 * 320;
    #pragma unroll
    for (int i = 0; i < 4; i++) {
        int m = bm + (ty << 2) + i;
        #pragma unroll
        for (int j = 0; j < 4; j++) {
            int nl = (tx << 2) + j;
            if (bn + nl < matN) prow[(size_t)m * 320 + coff + nl] = acc[i][j];
        }
    }
}

__global__ void s1_reduce_kernel(const float* __restrict__ part,
                                 float* __restrict__ gt, float* __restrict__ at,
                                 float* __restrict__ wt, float* __restrict__ vt)
{
    int m = blockIdx.x, c = threadIdx.x;
    float s = 0.f;
    #pragma unroll
    for (int z = 0; z < 8; z++) s += part[((size_t)z * 1024 + m) * 320 + c];
    if (c < 128)      gt[(size_t)m * 128 + c]        = 1.f / (1.f + expf(-s));
    else if (c < 192) at[(size_t)m * 64 + (c - 128)] = s;
    else if (c < 256) wt[(size_t)m * 64 + (c - 192)] = tanhf(s);
    else              vt[(size_t)m * 32 + (c - 256)] = s;
}

// ---------------- fused LayerNorm + token-shift mixing + bf16 splits ----------------
// Block t computes LN(x[t]) and LN(x[t-1]) (redundant), then all mixes for token t.
__global__ void lnmix_kernel(const float* __restrict__ x, const float* __restrict__ s1,
                             const float* __restrict__ lnw, const float* __restrict__ lnb,
                             const float* __restrict__ cr, const float* __restrict__ cw,
                             const float* __restrict__ ck, const float* __restrict__ cv,
                             const float* __restrict__ ca, const float* __restrict__ cg,
                             __nv_bfloat16* __restrict__ xrh, __nv_bfloat16* __restrict__ xrl,
                             __nv_bfloat16* __restrict__ xkh, __nv_bfloat16* __restrict__ xkl,
                             __nv_bfloat16* __restrict__ xvh, __nv_bfloat16* __restrict__ xvl,
                             float* __restrict__ oxw, float* __restrict__ oxv,
                             float* __restrict__ oxa, float* __restrict__ oxg,
                             float* __restrict__ s1out)
{
    __shared__ float sred[8];
    const int t = blockIdx.x;
    const int tid = threadIdx.x;

    // LN of token t
    const float* xr = x + (size_t)t * H_DIM;
    float v[8];
    float s = 0.f;
    #pragma unroll
    for (int j = 0; j < 8; j++) { v[j] = xr[tid + j * 256]; s += v[j]; }
    #pragma unroll
    for (int o = 16; o > 0; o >>= 1) s += __shfl_xor_sync(0xffffffffu, s, o);
    if ((tid & 31) == 0) sred[tid >> 5] = s;
    __syncthreads();
    float tot = 0.f;
    #pragma unroll
    for (int i = 0; i < 8; i++) tot += sred[i];
    const float mu = tot * (1.f / H_DIM);
    __syncthreads();
    float ss = 0.f;
    #pragma unroll
    for (int j = 0; j < 8; j++) { float d = v[j] - mu; ss += d * d; }
    #pragma unroll
    for (int o = 16; o > 0; o >>= 1) ss += __shfl_xor_sync(0xffffffffu, ss, o);
    if ((tid & 31) == 0) sred[tid >> 5] = ss;
    __syncthreads();
    tot = 0.f;
    #pragma unroll
    for (int i = 0; i < 8; i++) tot += sred[i];
    const float inv = rsqrtf(tot * (1.f / H_DIM) + 1e-5f);

    // LN of token t-1 (or raw state1 for t==0)
    float pv[8];
    float pmu = 0.f, pinv = 0.f;
    if (t > 0) {
        const float* xp = x + (size_t)(t - 1) * H_DIM;
        float s2 = 0.f;
        #pragma unroll
        for (int j = 0; j < 8; j++) { pv[j] = xp[tid + j * 256]; s2 += pv[j]; }
        #pragma unroll
        for (int o = 16; o > 0; o >>= 1) s2 += __shfl_xor_sync(0xffffffffu, s2, o);
        __syncthreads();
        if ((tid & 31) == 0) sred[tid >> 5] = s2;
        __syncthreads();
        float t2 = 0.f;
        #pragma unroll
        for (int i = 0; i < 8; i++) t2 += sred[i];
        pmu = t2 * (1.f / H_DIM);
        __syncthreads();
        float ss2 = 0.f;
        #pragma unroll
        for (int j = 0; j < 8; j++) { float d = pv[j] - pmu; ss2 += d * d; }
        #pragma unroll
        for (int o = 16; o > 0; o >>= 1) ss2 += __shfl_xor_sync(0xffffffffu, ss2, o);
        if ((tid & 31) == 0) sred[tid >> 5] = ss2;
        __syncthreads();
        t2 = 0.f;
        #pragma unroll
        for (int i = 0; i < 8; i++) t2 += sred[i];
        pinv = rsqrtf(t2 * (1.f / H_DIM) + 1e-5f);
    }

    #pragma unroll
    for (int j = 0; j < 8; j++) {
        int h = tid + j * 256;
        size_t idx = (size_t)t * H_DIM + h;
        float cur = (v[j] - mu) * inv * lnw[h] + lnb[h];
        float prev = (t > 0) ? ((pv[j] - pmu) * pinv * lnw[h] + lnb[h]) : s1[h];
        if (s1out != nullptr && t == T_LEN - 1) s1out[h] = cur;
        float sx = prev - cur;
        float xrv = cur + cr[h] * sx;
        float xkv = cur + ck[h] * sx;
        float xvv = cur + cv[h] * sx;
        oxw[idx] = cur + cw[h] * sx;
        oxv[idx] = xvv;
        oxa[idx] = cur + ca[h] * sx;
        oxg[idx] = cur + cg[h] * sx;
        __nv_bfloat16 hh;
        hh = __float2bfloat16(xrv); xrh[idx] = hh; xrl[idx] = __float2bfloat16(xrv - __bfloat162float(hh));
        hh = __float2bfloat16(xkv); xkh[idx] = hh; xkl[idx] = __float2bfloat16(xkv - __bfloat162float(hh));
        hh = __float2bfloat16(xvv); xvh[idx] = hh; xvl[idx] = __float2bfloat16(xvv - __bfloat162float(hh));
    }
}

// ---------------- small helpers ----------------
__device__ __forceinline__ float blockSum64(float v)
{
    __shared__ float sred[2];
    #pragma unroll
    for (int o = 16; o > 0; o >>= 1) v += __shfl_xor_sync(0xffffffffu, v, o);
    if ((threadIdx.x & 31) == 0) sred[threadIdx.x >> 5] = v;
    __syncthreads();
    float r = sred[0] + sred[1];
    __syncthreads();
    return r;
}

// prep (t-range): 256 threads handle 4 (t,h) records
__global__ void prep_kernel(const float* __restrict__ kbuf, const float* __restrict__ abuf,
                            const float* __restrict__ vbuf, const float* __restrict__ vmix,
                            const float* __restrict__ v_first,
                            const float* __restrict__ rbuf, const float* __restrict__ wbuf,
                            const float* __restrict__ k_k, const float* __restrict__ k_a,
                            float* __restrict__ pk, int rec0)
{
    __shared__ float sred[8];
    const int tid = threadIdx.x;
    const int rl = tid >> 6;
    const int rec_id = rec0 + blockIdx.x * 4 + rl;
    const int t = rec_id >> 5, h = rec_id & 31;
    const int i = tid & 63;
    const int g = h * HSZ + i;
    size_t idx = (size_t)t * H_DIM + g;
    float kv = kbuf[idx];
    float kkv = kv * k_k[g];
    float v2 = kkv * kkv;
    #pragma unroll
    for (int o = 16; o > 0; o >>= 1) v2 += __shfl_xor_sync(0xffffffffu, v2, o);
    if ((tid & 31) == 0) sred[tid >> 5] = v2;
    __syncthreads();
    float ss = sred[rl * 2] + sred[rl * 2 + 1];
    float kkn = kkv / (sqrtf(ss) + 1e-12f);
    float av = abuf[idx];
    float vv = vbuf[idx];
    float* rec = pk + (size_t)rec_id * 384;
    rec[i]         = rbuf[idx];
    rec[64 + i]    = wbuf[idx];
    rec[128 + i]   = kv * (1.f + (av - 1.f) * k_a[g]);
    rec[192 + i]   = -kkn;
    rec[256 + i]   = kkn * av;
    rec[320 + i]   = vv + (v_first[idx] - vv) * vmix[idx];
}

// ---------------- chunked WKV7 scan (range [t0, t1)) ----------------
#define SCH 16
__global__ void __launch_bounds__(128) scan_kernel(const float* __restrict__ pk,
                                                   const float* __restrict__ s2in,
                                                   float* __restrict__ ybuf,
                                                   float* __restrict__ s2out,
                                                   int t0, int t1)
{
    __shared__ __align__(16) float buf[2][SCH * 384];
    const int h = blockIdx.x >> 2, rg = blockIdx.x & 3;
    const int tid = threadIdx.x;
    const int rowh = rg * 16 + (tid >> 3);
    const int sub = tid & 7;
    const int c0 = sub * 8;
    const int cBeg = t0 / SCH, cEnd = t1 / SCH;
    float S[8];
    {
        const float* p = s2in + (size_t)h * 4096 + (size_t)rowh * 64 + c0;
        #pragma unroll
        for (int j = 0; j < 8; j++) S[j] = p[j];
    }
    auto issue = [&](int c) {
        float* dst = buf[c & 1];
        #pragma unroll
        for (int i = 0; i < 12; i++) {
            int o = tid + i * 128;
            int s = o / 96, w = o - s * 96;
            const float* src = pk + ((size_t)(c * SCH + s) * NHEAD + h) * 384 + w * 4;
            uint32_t d = (uint32_t)__cvta_generic_to_shared(dst + s * 384 + w * 4);
            asm volatile("cp.async.cg.shared.global [%0], [%1], 16;" :: "r"(d), "l"(src));
        }
        asm volatile("cp.async.commit_group;");
    };
    issue(cBeg);
    for (int c = cBeg; c < cEnd; c++) {
        asm volatile("cp.async.wait_group 0;");
        __syncthreads();
        if (c < cEnd - 1) issue(c + 1);
        const float* bp = buf[c & 1];
        #pragma unroll 4
        for (int s = 0; s < SCH; s++) {
            const float* rec = bp + s * 384;
            const float4 w0 = *(const float4*)(rec + 64 + c0);
            const float4 w1 = *(const float4*)(rec + 64 + c0 + 4);
            const float4 a0 = *(const float4*)(rec + 192 + c0);
            const float4 a1 = *(const float4*)(rec + 192 + c0 + 4);
            S[0] *= w0.x; S[1] *= w0.y; S[2] *= w0.z; S[3] *= w0.w;
            S[4] *= w1.x; S[5] *= w1.y; S[6] *= w1.z; S[7] *= w1.w;
            float p0 = S[0] * a0.x, p1 = S[1] * a0.y;
            p0 = fmaf(S[2], a0.z, p0); p1 = fmaf(S[3], a0.w, p1);
            p0 = fmaf(S[4], a1.x, p0); p1 = fmaf(S[5], a1.y, p1);
            p0 = fmaf(S[6], a1.z, p0); p1 = fmaf(S[7], a1.w, p1);
            float sa = p0 + p1;
            sa += __shfl_xor_sync(0xffffffffu, sa, 1);
            sa += __shfl_xor_sync(0xffffffffu, sa, 2);
            sa += __shfl_xor_sync(0xffffffffu, sa, 4);
            const float vi = rec[320 + rowh];
            const float4 k0 = *(const float4*)(rec + 128 + c0);
            const float4 k1 = *(const float4*)(rec + 128 + c0 + 4);
            const float4 b0 = *(const float4*)(rec + 256 + c0);
            const float4 b1 = *(const float4*)(rec + 256 + c0 + 4);
            const float4 r0 = *(const float4*)(rec + c0);
            const float4 r1 = *(const float4*)(rec + c0 + 4);
            S[0] = fmaf(sa, b0.x, fmaf(vi, k0.x, S[0]));
            S[1] = fmaf(sa, b0.y, fmaf(vi, k0.y, S[1]));
            S[2] = fmaf(sa, b0.z, fmaf(vi, k0.z, S[2]));
            S[3] = fmaf(sa, b0.w, fmaf(vi, k0.w, S[3]));
            S[4] = fmaf(sa, b1.x, fmaf(vi, k1.x, S[4]));
            S[5] = fmaf(sa, b1.y, fmaf(vi, k1.y, S[5]));
            S[6] = fmaf(sa, b1.z, fmaf(vi, k1.z, S[6]));
            S[7] = fmaf(sa, b1.w, fmaf(vi, k1.w, S[7]));
            float q0 = S[0] * r0.x, q1 = S[1] * r0.y;
            q0 = fmaf(S[2], r0.z, q0); q1 = fmaf(S[3], r0.w, q1);
            q0 = fmaf(S[4], r1.x, q0); q1 = fmaf(S[5], r1.y, q1);
            q0 = fmaf(S[6], r1.z, q0); q1 = fmaf(S[7], r1.w, q1);
            float y = q0 + q1;
            y += __shfl_xor_sync(0xffffffffu, y, 1);
            y += __shfl_xor_sync(0xffffffffu, y, 2);
            y += __shfl_xor_sync(0xffffffffu, y, 4);
            if (sub == 0)
                ybuf[(size_t)(c * SCH + s) * H_DIM + h * HSZ + rowh] = y;
        }
        __syncthreads();
    }
    if (s2out != nullptr) {
        float* p = s2out + (size_t)h * 4096 + (size_t)rowh * 64 + c0;
        #pragma unroll
        for (int j = 0; j < 8; j++) p[j] = S[j];
    }
}

// ---------------- GroupNorm + bonus + gate + bf16 split of op (range) ----------------
__global__ void post_kernel(const float* __restrict__ ybuf, const float* __restrict__ pk,
                            const float* __restrict__ gb, const float* __restrict__ r_k,
                            const float* __restrict__ lnw, const float* __restrict__ lnb,
                            __nv_bfloat16* __restrict__ oph, __nv_bfloat16* __restrict__ opl,
                            int t0)
{
    int t = t0 + (blockIdx.x >> 5);
    int h = blockIdx.x & 31;
    int i = threadIdx.x;
    int g = h * HSZ + i;
    size_t idx = (size_t)t * H_DIM + g;
    const float* rec = pk + ((size_t)t * NHEAD + h) * 384;
    float y = ybuf[idx];
    float mu = blockSum64(y) * (1.f / 64.f);
    float d = y - mu;
    float var = blockSum64(d * d) * (1.f / 64.f);
    float yn = d * rsqrtf(var + 0.00064f);
    float yv = yn * lnw[g] + lnb[g];
    float bon = blockSum64(rec[i] * rec[128 + i] * r_k[g]);
    float op = (yv + bon * rec[320 + i]) * gb[idx];
    __nv_bfloat16 hh = __float2bfloat16(op);
    oph[idx] = hh;
    opl[idx] = __float2bfloat16(op - __bfloat162float(hh));
}

__global__ void copy_kernel(const float* __restrict__ src, float* __restrict__ dst, size_t n)
{
    size_t i = (size_t)blockIdx.x * blockDim.x + threadIdx.x;
    if (i < n) dst[i] = src[i];
}

// ---------------------------------------------------------------------------
extern "C" void kernel_launch(void* const* d_in, const int* in_sizes, int n_in,
                              void* d_out, int out_size)
{
    const float* x       = (const float*)d_in[0];
    const float* state1  = (const float*)d_in[1];
    const float* state2  = (const float*)d_in[2];
    const float* v_first = (const float*)d_in[3];
    const float* x_r     = (const float*)d_in[4];
    const float* x_w     = (const float*)d_in[5];
    const float* x_k     = (const float*)d_in[6];
    const float* x_v     = (const float*)d_in[7];
    const float* x_a     = (const float*)d_in[8];
    const float* x_g     = (const float*)d_in[9];
    const float* W_r     = (const float*)d_in[10];
    const float* W_k     = (const float*)d_in[11];
    const float* W_v     = (const float*)d_in[12];
    const float* W_o     = (const float*)d_in[13];
    const float* w0      = (const float*)d_in[14];
    const float* w1      = (const float*)d_in[15];
    const float* w2      = (const float*)d_in[16];
    const float* a0      = (const float*)d_in[17];
    const float* a1      = (const float*)d_in[18];
    const float* a2      = (const float*)d_in[19];
    const float* v0      = (const float*)d_in[20];
    const float* v1      = (const float*)d_in[21];
    const float* v2      = (const float*)d_in[22];
    const float* g1      = (const float*)d_in[23];
    const float* g2      = (const float*)d_in[24];
    const float* k_k     = (const float*)d_in[25];
    const float* k_a     = (const float*)d_in[26];
    const float* r_k     = (const float*)d_in[27];
    const float* ln_x_w  = (const float*)d_in[28];
    const float* ln_x_b  = (const float*)d_in[29];
    const float* ln1_w   = (const float*)d_in[30];
    const float* ln1_b   = (const float*)d_in[31];

    float* sc = nullptr;
    cudaGetSymbolAddress((void**)&sc, d_scratch);
    __nv_bfloat16* bf = (__nv_bfloat16*)(sc + OFS_BF16);

    float* p_xw   = sc + OFS_XW;
    float* p_xv   = sc + OFS_XV;
    float* p_xa   = sc + OFS_XA;
    float* p_xg   = sc + OFS_XG;
    float* p_r    = sc + OFS_R;
    float* p_k    = sc + OFS_K;
    float* p_v    = sc + OFS_V;
    float* p_g    = sc + OFS_G;
    float* p_a    = sc + OFS_A;
    float* p_wd   = sc + OFS_WD;
    float* p_vm   = sc + OFS_VM;
    float* p_y    = sc + OFS_Y;
    float* p_gt   = sc + OFS_GT;
    float* p_at   = sc + OFS_AT;
    float* p_wt   = sc + OFS_WT;
    float* p_vt   = sc + OFS_VT;
    float* p_pt   = sc + OFS_PART;
    float* p_s2m  = sc + OFS_S2M;
    float* p_pk   = sc + OFS_PK;

    float* out = (float*)d_out;
    const size_t nMain = TH;
    const size_t nS1   = H_DIM;
    const size_t nS2   = (size_t)NHEAD * HSZ * HSZ;
    float* o_s1 = ((size_t)out_size >= nMain + nS1)            ? out + nMain             : nullptr;
    float* o_s2 = ((size_t)out_size >= nMain + nS1 + nS2)      ? out + nMain + nS1       : nullptr;
    float* o_vf = ((size_t)out_size >= nMain + nS1 + nS2 + TH) ? out + nMain + nS1 + nS2 : nullptr;

    static cudaStream_t s2s = nullptr, s3s = nullptr;
    static cudaEvent_t eF = nullptr, eC = nullptr, eC2 = nullptr, eM = nullptr,
                       eS = nullptr, eG = nullptr, eB = nullptr, eP2 = nullptr,
                       eS1 = nullptr, eJ = nullptr;
    if (s2s == nullptr) {
        cudaStreamCreateWithFlags(&s2s, cudaStreamNonBlocking);
        cudaStreamCreateWithFlags(&s3s, cudaStreamNonBlocking);
        cudaEventCreateWithFlags(&eF, cudaEventDisableTiming);
        cudaEventCreateWithFlags(&eC, cudaEventDisableTiming);
        cudaEventCreateWithFlags(&eC2, cudaEventDisableTiming);
        cudaEventCreateWithFlags(&eM, cudaEventDisableTiming);
        cudaEventCreateWithFlags(&eS, cudaEventDisableTiming);
        cudaEventCreateWithFlags(&eG, cudaEventDisableTiming);
        cudaEventCreateWithFlags(&eB, cudaEventDisableTiming);
        cudaEventCreateWithFlags(&eP2, cudaEventDisableTiming);
        cudaEventCreateWithFlags(&eS1, cudaEventDisableTiming);
        cudaEventCreateWithFlags(&eJ, cudaEventDisableTiming);
        cudaFuncSetAttribute(mma_gemm_kernel, cudaFuncAttributeMaxDynamicSharedMemorySize, GEMM_SMEM);
    }

    // ---- fork ----
    cudaEventRecord(eF, 0);
    cudaStreamWaitEvent(s2s, eF, 0);
    cudaStreamWaitEvent(s3s, eF, 0);

    // s2s: weight cvt, then MLP chain, then prep2
    cvt3_kernel<<<dim3(4096, 3), 256, 0, s2s>>>(W_r, W_k, W_v, bf);
    cudaEventRecord(eC, s2s);
    cvt_kernel<<<4096, 256, 0, s2s>>>(W_o, bf + BO_WOH, bf + BO_WOL);
    if (o_vf != nullptr) copy_kernel<<<4096, 512, 0, s2s>>>(v_first, o_vf, TH);
    cudaEventRecord(eC2, s2s);

    // main: fused LN+mix
    lnmix_kernel<<<T_LEN, 256>>>(x, state1, ln1_w, ln1_b, x_r, x_w, x_k, x_v, x_a, x_g,
                                 bf + BO_XRH, bf + BO_XRL, bf + BO_XKH, bf + BO_XKL,
                                 bf + BO_XVH, bf + BO_XVL, p_xw, p_xv, p_xa, p_xg, o_s1);
    cudaEventRecord(eM, 0);

    // s2s: MLP chain
    cudaStreamWaitEvent(s2s, eM, 0);
    s1_splitk_kernel<<<dim3(5, 16, 8), 256, 0, s2s>>>(p_xg, p_xa, p_xw, p_xv, g1, a1, w1, v1, p_pt);
    s1_reduce_kernel<<<1024, 288, 0, s2s>>>(p_pt, p_gt, p_at, p_wt, p_vt);
    s2_gemm_kernel<<<dim3(32, 16, 3), 256, 0, s2s>>>(p_gt, p_at, p_wt, p_vt,
                                                     g2, a2, w2, v2, a0, w0, v0,
                                                     p_g, p_a, p_wd, p_vm, 1);
    cudaEventRecord(eS, s2s);
    s2_gemm_kernel<<<dim3(32, 16, 1), 256, 0, s2s>>>(p_gt, p_at, p_wt, p_vt,
                                                     g2, a2, w2, v2, a0, w0, v0,
                                                     p_g, p_a, p_wd, p_vm, 0);
    cudaEventRecord(eG, s2s);

    // GEMM args (front projections)
    GemmArgs ga;
    ga.Ah[0] = bf + BO_XRH; ga.Al[0] = bf + BO_XRL; ga.Bh[0] = bf + BO_WRH; ga.Bl[0] = bf + BO_WRL;
    ga.Ah[1] = bf + BO_XKH; ga.Al[1] = bf + BO_XKL; ga.Bh[1] = bf + BO_WKH; ga.Bl[1] = bf + BO_WKL;
    ga.Ah[2] = bf + BO_XVH; ga.Al[2] = bf + BO_XVL; ga.Bh[2] = bf + BO_WVH; ga.Bl[2] = bf + BO_WVL;
    ga.C[0] = p_r; ga.C[1] = p_k; ga.C[2] = p_v;
    ga.R[0] = ga.R[1] = ga.R[2] = nullptr;

    // main: front GEMM half A (t<512) — created first so its CTAs dispatch first
    cudaStreamWaitEvent(0, eC, 0);
    {
        GemmArgs gA = ga; gA.m0 = 0;
        mma_gemm_kernel<<<dim3(16, 4, 3), 256, GEMM_SMEM>>>(gA);
    }
    // s3s: front GEMM half B (t>=512), concurrent, drains after A
    cudaStreamWaitEvent(s3s, eC, 0);
    cudaStreamWaitEvent(s3s, eM, 0);
    {
        GemmArgs gB = ga; gB.m0 = 512;
        mma_gemm_kernel<<<dim3(16, 4, 3), 256, GEMM_SMEM, s3s>>>(gB);
    }
    cudaEventRecord(eB, s3s);

    // main: prep1 + scan1 (t<512) — overlap with GEMM half B
    cudaStreamWaitEvent(0, eS, 0);
    prep_kernel<<<4096, 256>>>(p_k, p_a, p_v, p_vm, v_first, p_r, p_wd, k_k, k_a, p_pk, 0);
    scan_kernel<<<128, 128>>>(p_pk, state2, p_y, p_s2m, 0, 512);
    cudaEventRecord(eS1, 0);

    // s2s: prep2 (t>=512) after GEMM half B
    cudaStreamWaitEvent(s2s, eB, 0);
    prep_kernel<<<4096, 256, 0, s2s>>>(p_k, p_a, p_v, p_vm, v_first, p_r, p_wd, k_k, k_a,
                                       p_pk, 512 * NHEAD);
    cudaEventRecord(eP2, s2s);

    // main: scan2
    cudaStreamWaitEvent(0, eP2, 0);
    scan_kernel<<<128, 128>>>(p_pk, p_s2m, p_y, o_s2, 512, 1024);

    // W_o GEMM args
    GemmArgs go;
    go.Ah[0] = bf + BO_OPH; go.Al[0] = bf + BO_OPL; go.Bh[0] = bf + BO_WOH; go.Bl[0] = bf + BO_WOL;
    go.Ah[1] = go.Ah[0]; go.Al[1] = go.Al[0]; go.Bh[1] = go.Bh[0]; go.Bl[1] = go.Bl[0];
    go.Ah[2] = go.Ah[0]; go.Al[2] = go.Al[0]; go.Bh[2] = go.Bh[0]; go.Bl[2] = go.Bl[0];
    go.C[0] = out; go.C[1] = out; go.C[2] = out;
    go.R[0] = x; go.R[1] = x; go.R[2] = x;

    // s3s: post1 + Wo1 (t<512) overlapped with scan2
    cudaStreamWaitEvent(s3s, eS1, 0);
    cudaStreamWaitEvent(s3s, eG, 0);
    post_kernel<<<512 * NHEAD, 64, 0, s3s>>>(p_y, p_pk, p_g, r_k, ln_x_w, ln_x_b,
                                             bf + BO_OPH, bf + BO_OPL, 0);
    cudaStreamWaitEvent(s3s, eC2, 0);
    {
        GemmArgs g0 = go; g0.m0 = 0;
        mma_gemm_kernel<<<dim3(16, 4, 1), 256, GEMM_SMEM, s3s>>>(g0);
    }
    cudaEventRecord(eJ, s3s);

    // main: post2 + Wo2 (t>=512)
    cudaStreamWaitEvent(0, eG, 0);
    post_kernel<<<512 * NHEAD, 64>>>(p_y, p_pk, p_g, r_k, ln_x_w, ln_x_b,
                                     bf + BO_OPH, bf + BO_OPL, 512);
    cudaStreamWaitEvent(0, eC2, 0);
    {
        GemmArgs g1a = go; g1a.m0 = 512;
        mma_gemm_kernel<<<dim3(16, 4, 1), 256, GEMM_SMEM>>>(g1a);
    }

    // join
    cudaStreamWaitEvent(0, eJ, 0);
}

// round 16
// speedup vs baseline: 1.1283x; 1.1283x over previous
#include <cuda_runtime.h>
#include <cuda_bf16.h>
#include <math.h>
#include <cstdint>

#define T_LEN 1024
#define H_DIM 2048
#define NHEAD 32
#define HSZ   64

static const size_t TH = (size_t)T_LEN * H_DIM;

// ---------------- scratch layout (float units) ----------------
#define THF 2097152ull
#define OFS_XN   (0*THF)
#define OFS_XW   (1*THF)
#define OFS_XV   (2*THF)
#define OFS_XA   (3*THF)
#define OFS_XG   (4*THF)
#define OFS_R    (5*THF)
#define OFS_K    (6*THF)
#define OFS_V    (7*THF)
#define OFS_G    (8*THF)
#define OFS_A    (9*THF)
#define OFS_WD   (10*THF)
#define OFS_VM   (11*THF)
#define OFS_Y    (12*THF)
#define OFS_GT   (13*THF)
#define OFS_AT   (OFS_GT + 131072ull)
#define OFS_WT   (OFS_AT + 65536ull)
#define OFS_VT   (OFS_WT + 65536ull)
#define OFS_PART (OFS_VT + 32768ull)              // 8*1024*320 floats
#define OFS_S2M  (OFS_PART + 2621440ull)          // mid-scan state 32*64*64
#define OFS_BF16 (OFS_S2M + 131072ull)            // bf16 region (float units)
#define BO_WRH 0ull
#define BO_WRL 4194304ull
#define BO_WKH 8388608ull
#define BO_WKL 12582912ull
#define BO_WVH 16777216ull
#define BO_WVL 20971520ull
#define BO_WOH 25165824ull
#define BO_WOL 29360128ull
#define BO_XRH 33554432ull
#define BO_XRL 35651584ull
#define BO_XKH 37748736ull
#define BO_XKL 39845888ull
#define BO_XVH 41943040ull
#define BO_XVL 44040192ull
#define BO_OPH 46137344ull
#define BO_OPL 48234496ull
#define BF16_ELEMS 50331648ull
#define OFS_PK   (OFS_BF16 + BF16_ELEMS/2)        // packed scan ops
#define SCRATCH_FLOATS (OFS_PK + 12582912ull)

__device__ __align__(1024) float d_scratch[SCRATCH_FLOATS];

// ---------------- mma.sync helpers ----------------
__device__ __forceinline__ void ldmat4(uint32_t* r, uint32_t addr) {
    asm volatile("ldmatrix.sync.aligned.m8n8.x4.shared.b16 {%0,%1,%2,%3}, [%4];"
        : "=r"(r[0]), "=r"(r[1]), "=r"(r[2]), "=r"(r[3]) : "r"(addr));
}
__device__ __forceinline__ void mma16816(float* d, const uint32_t* a, const uint32_t* b) {
    asm volatile("mma.sync.aligned.m16n8k16.row.col.f32.bf16.bf16.f32 "
        "{%0,%1,%2,%3}, {%4,%5,%6,%7}, {%8,%9}, {%0,%1,%2,%3};"
        : "+f"(d[0]), "+f"(d[1]), "+f"(d[2]), "+f"(d[3])
        : "r"(a[0]), "r"(a[1]), "r"(a[2]), "r"(a[3]), "r"(b[0]), "r"(b[1]));
}

// ---------------- fp32 -> bf16 hi/lo split ----------------
__global__ void cvt_kernel(const float* __restrict__ x, __nv_bfloat16* __restrict__ hi,
                           __nv_bfloat16* __restrict__ lo)
{
    int i = blockIdx.x * blockDim.x + threadIdx.x;
    float4 v = ((const float4*)x)[i];
    float a[4] = {v.x, v.y, v.z, v.w};
    __nv_bfloat16 h[4], l[4];
    #pragma unroll
    for (int j = 0; j < 4; j++) {
        h[j] = __float2bfloat16(a[j]);
        l[j] = __float2bfloat16(a[j] - __bfloat162float(h[j]));
    }
    ((__nv_bfloat162*)hi)[2*i]   = __nv_bfloat162(h[0], h[1]);
    ((__nv_bfloat162*)hi)[2*i+1] = __nv_bfloat162(h[2], h[3]);
    ((__nv_bfloat162*)lo)[2*i]   = __nv_bfloat162(l[0], l[1]);
    ((__nv_bfloat162*)lo)[2*i+1] = __nv_bfloat162(l[2], l[3]);
}

__global__ void cvt3_kernel(const float* __restrict__ w0, const float* __restrict__ w1,
                            const float* __restrict__ w2, __nv_bfloat16* __restrict__ bfbase)
{
    int which = blockIdx.y;
    const float* x; __nv_bfloat16 *hi, *lo;
    if (which == 0)      { x = w0; hi = bfbase + BO_WRH; lo = bfbase + BO_WRL; }
    else if (which == 1) { x = w1; hi = bfbase + BO_WKH; lo = bfbase + BO_WKL; }
    else                 { x = w2; hi = bfbase + BO_WVH; lo = bfbase + BO_WVL; }
    int i = blockIdx.x * blockDim.x + threadIdx.x;
    float4 v = ((const float4*)x)[i];
    float a[4] = {v.x, v.y, v.z, v.w};
    __nv_bfloat16 h[4], l[4];
    #pragma unroll
    for (int j = 0; j < 4; j++) {
        h[j] = __float2bfloat16(a[j]);
        l[j] = __float2bfloat16(a[j] - __bfloat162float(h[j]));
    }
    ((__nv_bfloat162*)hi)[2*i]   = __nv_bfloat162(h[0], h[1]);
    ((__nv_bfloat162*)hi)[2*i+1] = __nv_bfloat162(h[2], h[3]);
    ((__nv_bfloat162*)lo)[2*i]   = __nv_bfloat162(l[0], l[1]);
    ((__nv_bfloat162*)lo)[2*i+1] = __nv_bfloat162(l[2], l[3]);
}

// ---------------- HMMA split-bf16 GEMM (3-stage) ----------------
#define SROW 144
#define TILE_B (128*SROW)
#define S_ALO 18432
#define S_BHI 36864
#define S_BLO 55296
#define STAGE_B 73728
#define GEMM_SMEM (3*STAGE_B)

struct GemmArgs {
    const __nv_bfloat16 *Ah[3], *Al[3], *Bh[3], *Bl[3];
    float* C[3];
    const float* R[3];
    int m0;
};

__global__ void __launch_bounds__(256, 1)
mma_gemm_kernel(GemmArgs ga)
{
    extern __shared__ char smem[];
    const uint32_t sb = (uint32_t)__cvta_generic_to_shared(smem);
    const int tid = threadIdx.x;
    const int lane = tid & 31, wid = tid >> 5;
    const int wm = wid >> 2, wn = wid & 3;
    const int g = blockIdx.z;
    const int bm = ga.m0 + blockIdx.y * 128, bn = blockIdx.x * 128;
    const int lr = lane & 15, lc = lane >> 4;

    float acc[4][4][4];
    #pragma unroll
    for (int a = 0; a < 4; a++)
        #pragma unroll
        for (int b = 0; b < 4; b++)
            #pragma unroll
            for (int c = 0; c < 4; c++) acc[a][b][c] = 0.f;

    const __nv_bfloat16* gp[4];
    gp[0] = ga.Ah[g] + (size_t)bm * 2048;
    gp[1] = ga.Al[g] + (size_t)bm * 2048;
    gp[2] = ga.Bh[g] + (size_t)bn * 2048;
    gp[3] = ga.Bl[g] + (size_t)bn * 2048;

    auto issue = [&](int c) {
        uint32_t stage = sb + (uint32_t)(c % 3) * STAGE_B;
        const int kc = c * 64;
        #pragma unroll
        for (int t = 0; t < 4; t++) {
            #pragma unroll
            for (int i = 0; i < 4; i++) {
                int lin = tid + i * 256;
                int row = lin >> 3, seg = lin & 7;
                uint32_t s = stage + t * TILE_B + row * SROW + seg * 16;
                const __nv_bfloat16* gsrc = gp[t] + (size_t)row * 2048 + kc + seg * 8;
                asm volatile("cp.async.cg.shared.global [%0], [%1], 16;" :: "r"(s), "l"(gsrc));
            }
        }
        asm volatile("cp.async.commit_group;");
    };

    issue(0);
    issue(1);
    for (int c = 0; c < 32; c++) {
        if (c < 31) { asm volatile("cp.async.wait_group 1;"); }
        else        { asm volatile("cp.async.wait_group 0;"); }
        __syncthreads();
        if (c < 30) issue(c + 2);
        uint32_t stage = sb + (uint32_t)(c % 3) * STAGE_B;
        #pragma unroll
        for (int ks = 0; ks < 4; ks++) {
            const int kb2 = (ks * 16 + lc * 8) * 2;
            uint32_t ah[4][4], al[4][4], bh[4][2], bl[4][2];
            #pragma unroll
            for (int mt = 0; mt < 4; mt++) {
                uint32_t ro = (uint32_t)((wm * 64 + mt * 16 + lr) * SROW + kb2);
                ldmat4(ah[mt], stage + ro);
                ldmat4(al[mt], stage + S_ALO + ro);
            }
            #pragma unroll
            for (int j = 0; j < 2; j++) {
                uint32_t ro = (uint32_t)((wn * 32 + j * 16 + lr) * SROW + kb2);
                uint32_t r[4];
                ldmat4(r, stage + S_BHI + ro);
                bh[2*j][0] = r[0]; bh[2*j][1] = r[2];
                bh[2*j+1][0] = r[1]; bh[2*j+1][1] = r[3];
                ldmat4(r, stage + S_BLO + ro);
                bl[2*j][0] = r[0]; bl[2*j][1] = r[2];
                bl[2*j+1][0] = r[1]; bl[2*j+1][1] = r[3];
            }
            #pragma unroll
            for (int mt = 0; mt < 4; mt++)
                #pragma unroll
                for (int nt = 0; nt < 4; nt++)
                    mma16816(acc[mt][nt], ah[mt], bh[nt]);
            #pragma unroll
            for (int mt = 0; mt < 4; mt++)
                #pragma unroll
                for (int nt = 0; nt < 4; nt++)
                    mma16816(acc[mt][nt], ah[mt], bl[nt]);
            #pragma unroll
            for (int mt = 0; mt < 4; mt++)
                #pragma unroll
                for (int nt = 0; nt < 4; nt++)
                    mma16816(acc[mt][nt], al[mt], bh[nt]);
        }
        __syncthreads();
    }

    float* C = ga.C[g];
    const float* R = ga.R[g];
    #pragma unroll
    for (int mt = 0; mt < 4; mt++) {
        int r0 = bm + wm * 64 + mt * 16 + (lane >> 2);
        #pragma unroll
        for (int nt = 0; nt < 4; nt++) {
            int col = bn + wn * 32 + nt * 8 + (lane & 3) * 2;
            float2 v0 = make_float2(acc[mt][nt][0], acc[mt][nt][1]);
            float2 v1 = make_float2(acc[mt][nt][2], acc[mt][nt][3]);
            if (R != nullptr) {
                float2 q0 = *(const float2*)(R + (size_t)r0 * 2048 + col);
                float2 q1 = *(const float2*)(R + (size_t)(r0 + 8) * 2048 + col);
                v0.x += q0.x; v0.y += q0.y; v1.x += q1.x; v1.y += q1.y;
            }
            *(float2*)(C + (size_t)r0 * 2048 + col) = v0;
            *(float2*)(C + (size_t)(r0 + 8) * 2048 + col) = v1;
        }
    }
}

// ---------------- fused stage-2 SGEMM ----------------
__global__ void s2_gemm_kernel(const float* __restrict__ gt, const float* __restrict__ at,
                               const float* __restrict__ wt, const float* __restrict__ vt,
                               const float* __restrict__ g2, const float* __restrict__ a2,
                               const float* __restrict__ w2, const float* __restrict__ v2,
                               const float* __restrict__ a0, const float* __restrict__ w0,
                               const float* __restrict__ v0,
                               float* __restrict__ G, float* __restrict__ A,
                               float* __restrict__ W, float* __restrict__ V, int zoff)
{
    __shared__ float As[16][68];
    __shared__ float Bs[16][68];
    const float* Ain; const float* Bin; const float* bias; float* Cout;
    int K, mode;
    switch (blockIdx.z + zoff) {
        case 0:  Ain = gt; Bin = g2; Cout = G; bias = nullptr; K = 128; mode = 0; break;
        case 1:  Ain = at; Bin = a2; Cout = A; bias = a0;      K = 64;  mode = 3; break;
        case 2:  Ain = wt; Bin = w2; Cout = W; bias = w0;      K = 64;  mode = 4; break;
        default: Ain = vt; Bin = v2; Cout = V; bias = v0;      K = 32;  mode = 3; break;
    }
    const int N = H_DIM;
    const int tid = threadIdx.x;
    const int tx = tid & 15, ty = tid >> 4;
    const int bm = blockIdx.y * 64, bn = blockIdx.x * 64;
    float acc[4][4] = {};
    for (int k0 = 0; k0 < K; k0 += 16) {
        {
            int r = tid >> 2, c = (tid & 3) << 2;
            #pragma unroll
            for (int u = 0; u < 4; u++) {
                int gc = k0 + c + u;
                As[c + u][r] = (gc < K) ? Ain[(size_t)(bm + r) * K + gc] : 0.f;
            }
        }
        {
            int kr = tid >> 4, nc = (tid & 15) << 2;
            int gk = k0 + kr;
            #pragma unroll
            for (int u = 0; u < 4; u++)
                Bs[kr][nc + u] = (gk < K) ? Bin[(size_t)gk * N + bn + nc + u] : 0.f;
        }
        __syncthreads();
        #pragma unroll
        for (int kk = 0; kk < 16; kk++) {
            const float4 a4 = *(const float4*)&As[kk][ty << 2];
            const float4 b4 = *(const float4*)&Bs[kk][tx << 2];
            float a[4] = {a4.x, a4.y, a4.z, a4.w};
            float b[4] = {b4.x, b4.y, b4.z, b4.w};
            #pragma unroll
            for (int i = 0; i < 4; i++)
                #pragma unroll
                for (int j = 0; j < 4; j++)
                    acc[i][j] = fmaf(a[i], b[j], acc[i][j]);
        }
        __syncthreads();
    }
    #pragma unroll
    for (int i = 0; i < 4; i++) {
        int m = bm + (ty << 2) + i;
        #pragma unroll
        for (int j = 0; j < 4; j++) {
            int n = bn + (tx << 2) + j;
            float v = acc[i][j];
            if (mode == 3)      v = 1.f / (1.f + expf(-(bias[n] + v)));
            else if (mode == 4) v = expf(-0.606531f / (1.f + expf(-(bias[n] + v))));
            Cout[(size_t)m * N + n] = v;
        }
    }
}

// ---------------- stage-1 split-K GEMM ----------------
__global__ void __launch_bounds__(256) s1_splitk_kernel(
    const float* __restrict__ xg, const float* __restrict__ xa,
    const float* __restrict__ xw, const float* __restrict__ xv,
    const float* __restrict__ g1, const float* __restrict__ a1,
    const float* __restrict__ w1, const float* __restrict__ v1,
    float* __restrict__ part)
{
    __shared__ float As[16][68];
    __shared__ float Bs[16][68];
    const int tid = threadIdx.x, tx = tid & 15, ty = tid >> 4;
    const int bx = blockIdx.x;
    const float* A; const float* B; int matN, bn, coff;
    if (bx == 0)      { A = xg; B = g1; matN = 128; bn = 0;  coff = 0; }
    else if (bx == 1) { A = xg; B = g1; matN = 128; bn = 64; coff = 64; }
    else if (bx == 2) { A = xa; B = a1; matN = 64;  bn = 0;  coff = 128; }
    else if (bx == 3) { A = xw; B = w1; matN = 64;  bn = 0;  coff = 192; }
    else              { A = xv; B = v1; matN = 32;  bn = 0;  coff = 256; }
    const int bm = blockIdx.y * 64;
    const int kb = blockIdx.z * 256;
    float acc[4][4] = {};
    for (int k0 = kb; k0 < kb + 256; k0 += 16) {
        {
            int r = tid >> 2, c = (tid & 3) << 2;
            #pragma unroll
            for (int u = 0; u < 4; u++)
                As[c + u][r] = A[(size_t)(bm + r) * H_DIM + k0 + c + u];
        }
        {
            int kr = tid >> 4, nc = (tid & 15) << 2;
            #pragma unroll
            for (int u = 0; u < 4; u++) {
                int n = bn + nc + u;
                Bs[kr][nc + u] = (n < matN) ? B[(size_t)(k0 + kr) * matN + n] : 0.f;
            }
        }
        __syncthreads();
        #pragma unroll
        for (int kk = 0; kk < 16; kk++) {
            const float4 a4 = *(const float4*)&As[kk][ty << 2];
            const float4 b4 = *(const float4*)&Bs[kk][tx << 2];
            float a[4] = {a4.x, a4.y, a4.z, a4.w};
            float b[4] = {b4.x, b4.y, b4.z, b4.w};
            #pragma unroll
            for (int i = 0; i < 4; i++)
                #pragma unroll
                for (int j = 0; j < 4; j++)
                    acc[i][j] = fmaf(a[i], b[j], acc[i][j]);
        }
        __syncthreads();
    }
    float* prow = part + (size_t)blockIdx.z * 1024 * 320;
    #pragma unroll
    for (int i = 0; i < 4; i++) {
        int m = bm + (ty << 2) + i;
        #pragma unroll
        for (int j = 0; j < 4; j++) {
            int nl = (tx << 2) + j;
            if (bn + nl < matN) prow[(size_t)m * 320 + coff + nl] = acc[i][j];
        }
    }
}

__global__ void s1_reduce_kernel(const float* __restrict__ part,
                                 float* __restrict__ gt, float* __restrict__ at,
                                 float* __restrict__ wt, float* __restrict__ vt)
{
    int m = blockIdx.x, c = threadIdx.x;
    float s = 0.f;
    #pragma unroll
    for (int z = 0; z < 8; z++) s += part[((size_t)z * 1024 + m) * 320 + c];
    if (c < 128)      gt[(size_t)m * 128 + c]        = 1.f / (1.f + expf(-s));
    else if (c < 192) at[(size_t)m * 64 + (c - 128)] = s;
    else if (c < 256) wt[(size_t)m * 64 + (c - 192)] = tanhf(s);
    else              vt[(size_t)m * 32 + (c - 256)] = s;
}

// ---------------- LayerNorm ----------------
__global__ void ln1_kernel(const float* __restrict__ x, const float* __restrict__ w,
                           const float* __restrict__ b, float* __restrict__ xn,
                           float* __restrict__ s1out)
{
    __shared__ float sred[8];
    const int t = blockIdx.x;
    const int tid = threadIdx.x;
    const float* xr = x + (size_t)t * H_DIM;
    float v[8];
    float s = 0.f;
    #pragma unroll
    for (int j = 0; j < 8; j++) { v[j] = xr[tid + j * 256]; s += v[j]; }
    #pragma unroll
    for (int o = 16; o > 0; o >>= 1) s += __shfl_xor_sync(0xffffffffu, s, o);
    if ((tid & 31) == 0) sred[tid >> 5] = s;
    __syncthreads();
    float tot = 0.f;
    #pragma unroll
    for (int i = 0; i < 8; i++) tot += sred[i];
    const float mu = tot * (1.f / H_DIM);
    __syncthreads();
    float ss = 0.f;
    #pragma unroll
    for (int j = 0; j < 8; j++) { float d = v[j] - mu; ss += d * d; }
    #pragma unroll
    for (int o = 16; o > 0; o >>= 1) ss += __shfl_xor_sync(0xffffffffu, ss, o);
    if ((tid & 31) == 0) sred[tid >> 5] = ss;
    __syncthreads();
    tot = 0.f;
    #pragma unroll
    for (int i = 0; i < 8; i++) tot += sred[i];
    const float inv = rsqrtf(tot * (1.f / H_DIM) + 1e-5f);
    float* xo = xn + (size_t)t * H_DIM;
    #pragma unroll
    for (int j = 0; j < 8; j++) {
        int h = tid + j * 256;
        float val = (v[j] - mu) * inv * w[h] + b[h];
        xo[h] = val;
        if (s1out != nullptr && t == T_LEN - 1) s1out[h] = val;
    }
}

// ---------------- token-shift mixing + bf16 splits ----------------
__global__ void mix_kernel(const float* __restrict__ xn, const float* __restrict__ s1,
                           const float* __restrict__ cr, const float* __restrict__ cw,
                           const float* __restrict__ ck, const float* __restrict__ cv,
                           const float* __restrict__ ca, const float* __restrict__ cg,
                           __nv_bfloat16* __restrict__ xrh, __nv_bfloat16* __restrict__ xrl,
                           __nv_bfloat16* __restrict__ xkh, __nv_bfloat16* __restrict__ xkl,
                           __nv_bfloat16* __restrict__ xvh, __nv_bfloat16* __restrict__ xvl,
                           float* __restrict__ oxw, float* __restrict__ oxv,
                           float* __restrict__ oxa, float* __restrict__ oxg)
{
    size_t idx = (size_t)blockIdx.x * blockDim.x + threadIdx.x;
    int t = (int)(idx >> 11);
    int h = (int)(idx & 2047);
    float cur = xn[idx];
    float prev = t ? xn[idx - H_DIM] : s1[h];
    float sx = prev - cur;
    float xr = cur + cr[h] * sx;
    float xk = cur + ck[h] * sx;
    float xv = cur + cv[h] * sx;
    oxw[idx] = cur + cw[h] * sx;
    oxv[idx] = xv;
    oxa[idx] = cur + ca[h] * sx;
    oxg[idx] = cur + cg[h] * sx;
    __nv_bfloat16 hh;
    hh = __float2bfloat16(xr); xrh[idx] = hh; xrl[idx] = __float2bfloat16(xr - __bfloat162float(hh));
    hh = __float2bfloat16(xk); xkh[idx] = hh; xkl[idx] = __float2bfloat16(xk - __bfloat162float(hh));
    hh = __float2bfloat16(xv); xvh[idx] = hh; xvl[idx] = __float2bfloat16(xv - __bfloat162float(hh));
}

// ---------------- small helpers ----------------
__device__ __forceinline__ float blockSum64(float v)
{
    __shared__ float sred[2];
    #pragma unroll
    for (int o = 16; o > 0; o >>= 1) v += __shfl_xor_sync(0xffffffffu, v, o);
    if ((threadIdx.x & 31) == 0) sred[threadIdx.x >> 5] = v;
    __syncthreads();
    float r = sred[0] + sred[1];
    __syncthreads();
    return r;
}

// prep: 256 threads handle 4 (t,h) records; one sync for the 64-wide sums
__global__ void prep_kernel(const float* __restrict__ kbuf, const float* __restrict__ abuf,
                            const float* __restrict__ vbuf, const float* __restrict__ vmix,
                            const float* __restrict__ v_first,
                            const float* __restrict__ rbuf, const float* __restrict__ wbuf,
                            const float* __restrict__ k_k, const float* __restrict__ k_a,
                            float* __restrict__ pk)
{
    __shared__ float sred[8];
    const int tid = threadIdx.x;
    const int rl = tid >> 6;
    const int rec_id = blockIdx.x * 4 + rl;
    const int t = rec_id >> 5, h = rec_id & 31;
    const int i = tid & 63;
    const int g = h * HSZ + i;
    size_t idx = (size_t)t * H_DIM + g;
    float kv = kbuf[idx];
    float kkv = kv * k_k[g];
    float v2 = kkv * kkv;
    #pragma unroll
    for (int o = 16; o > 0; o >>= 1) v2 += __shfl_xor_sync(0xffffffffu, v2, o);
    if ((tid & 31) == 0) sred[tid >> 5] = v2;
    __syncthreads();
    float ss = sred[rl * 2] + sred[rl * 2 + 1];
    float kkn = kkv / (sqrtf(ss) + 1e-12f);
    float av = abuf[idx];
    float vv = vbuf[idx];
    float* rec = pk + (size_t)rec_id * 384;
    rec[i]         = rbuf[idx];
    rec[64 + i]    = wbuf[idx];
    rec[128 + i]   = kv * (1.f + (av - 1.f) * k_a[g]);
    rec[192 + i]   = -kkn;
    rec[256 + i]   = kkn * av;
    rec[320 + i]   = vv + (v_first[idx] - vv) * vmix[idx];
}

// ---------------- chunked WKV7 scan v3: 256 threads, 16 threads/row ----------------
#define SCH 16
__global__ void __launch_bounds__(256) scan_kernel(const float* __restrict__ pk,
                                                   const float* __restrict__ s2in,
                                                   float* __restrict__ ybuf,
                                                   float* __restrict__ s2out,
                                                   int t0, int t1)
{
    __shared__ __align__(16) float buf[2][SCH * 384];
    const int h = blockIdx.x >> 2, rg = blockIdx.x & 3;
    const int tid = threadIdx.x;
    const int rowh = rg * 16 + (tid >> 4);    // 16 rows per CTA
    const int sub = tid & 15;                 // 16 threads per row
    const int c0 = sub * 4;                   // 4 columns each
    const int cBeg = t0 / SCH, cEnd = t1 / SCH;
    float S[4];
    {
        const float* p = s2in + (size_t)h * 4096 + (size_t)rowh * 64 + c0;
        #pragma unroll
        for (int j = 0; j < 4; j++) S[j] = p[j];
    }
    auto issue = [&](int c) {
        float* dst = buf[c & 1];
        #pragma unroll
        for (int i = 0; i < 6; i++) {
            int o = tid + i * 256;
            int s = o / 96, w = o - s * 96;
            const float* src = pk + ((size_t)(c * SCH + s) * NHEAD + h) * 384 + w * 4;
            uint32_t d = (uint32_t)__cvta_generic_to_shared(dst + s * 384 + w * 4);
            asm volatile("cp.async.cg.shared.global [%0], [%1], 16;" :: "r"(d), "l"(src));
        }
        asm volatile("cp.async.commit_group;");
    };
    issue(cBeg);
    for (int c = cBeg; c < cEnd; c++) {
        asm volatile("cp.async.wait_group 0;");
        __syncthreads();
        if (c < cEnd - 1) issue(c + 1);
        const float* bp = buf[c & 1];
        #pragma unroll 4
        for (int s = 0; s < SCH; s++) {
            const float* rec = bp + s * 384;
            const float4 w4 = *(const float4*)(rec + 64 + c0);
            const float4 a4 = *(const float4*)(rec + 192 + c0);
            S[0] *= w4.x; S[1] *= w4.y; S[2] *= w4.z; S[3] *= w4.w;
            float p0 = S[0] * a4.x, p1 = S[1] * a4.y;
            p0 = fmaf(S[2], a4.z, p0); p1 = fmaf(S[3], a4.w, p1);
            float sa = p0 + p1;
            sa += __shfl_xor_sync(0xffffffffu, sa, 1);
            sa += __shfl_xor_sync(0xffffffffu, sa, 2);
            sa += __shfl_xor_sync(0xffffffffu, sa, 4);
            sa += __shfl_xor_sync(0xffffffffu, sa, 8);
            const float vi = rec[320 + rowh];
            const float4 k4 = *(const float4*)(rec + 128 + c0);
            const float4 b4 = *(const float4*)(rec + 256 + c0);
            const float4 r4 = *(const float4*)(rec + c0);
            S[0] = fmaf(sa, b4.x, fmaf(vi, k4.x, S[0]));
            S[1] = fmaf(sa, b4.y, fmaf(vi, k4.y, S[1]));
            S[2] = fmaf(sa, b4.z, fmaf(vi, k4.z, S[2]));
            S[3] = fmaf(sa, b4.w, fmaf(vi, k4.w, S[3]));
            float q0 = S[0] * r4.x, q1 = S[1] * r4.y;
            q0 = fmaf(S[2], r4.z, q0); q1 = fmaf(S[3], r4.w, q1);
            float y = q0 + q1;
            y += __shfl_xor_sync(0xffffffffu, y, 1);
            y += __shfl_xor_sync(0xffffffffu, y, 2);
            y += __shfl_xor_sync(0xffffffffu, y, 4);
            y += __shfl_xor_sync(0xffffffffu, y, 8);
            if (sub == 0)
                ybuf[(size_t)(c * SCH + s) * H_DIM + h * HSZ + rowh] = y;
        }
        __syncthreads();
    }
    if (s2out != nullptr) {
        float* p = s2out + (size_t)h * 4096 + (size_t)rowh * 64 + c0;
        #pragma unroll
        for (int j = 0; j < 4; j++) p[j] = S[j];
    }
}

// ---------------- GroupNorm + bonus + gate + bf16 split of op (range) ----------------
__global__ void post_kernel(const float* __restrict__ ybuf, const float* __restrict__ pk,
                            const float* __restrict__ gb, const float* __restrict__ r_k,
                            const float* __restrict__ lnw, const float* __restrict__ lnb,
                            __nv_bfloat16* __restrict__ oph, __nv_bfloat16* __restrict__ opl,
                            int t0)
{
    int t = t0 + (blockIdx.x >> 5);
    int h = blockIdx.x & 31;
    int i = threadIdx.x;
    int g = h * HSZ + i;
    size_t idx = (size_t)t * H_DIM + g;
    const float* rec = pk + ((size_t)t * NHEAD + h) * 384;
    float y = ybuf[idx];
    float mu = blockSum64(y) * (1.f / 64.f);
    float d = y - mu;
    float var = blockSum64(d * d) * (1.f / 64.f);
    float yn = d * rsqrtf(var + 0.00064f);
    float yv = yn * lnw[g] + lnb[g];
    float bon = blockSum64(rec[i] * rec[128 + i] * r_k[g]);
    float op = (yv + bon * rec[320 + i]) * gb[idx];
    __nv_bfloat16 hh = __float2bfloat16(op);
    oph[idx] = hh;
    opl[idx] = __float2bfloat16(op - __bfloat162float(hh));
}

__global__ void copy_kernel(const float* __restrict__ src, float* __restrict__ dst, size_t n)
{
    size_t i = (size_t)blockIdx.x * blockDim.x + threadIdx.x;
    if (i < n) dst[i] = src[i];
}

// ---------------------------------------------------------------------------
extern "C" void kernel_launch(void* const* d_in, const int* in_sizes, int n_in,
                              void* d_out, int out_size)
{
    const float* x       = (const float*)d_in[0];
    const float* state1  = (const float*)d_in[1];
    const float* state2  = (const float*)d_in[2];
    const float* v_first = (const float*)d_in[3];
    const float* x_r     = (const float*)d_in[4];
    const float* x_w     = (const float*)d_in[5];
    const float* x_k     = (const float*)d_in[6];
    const float* x_v     = (const float*)d_in[7];
    const float* x_a     = (const float*)d_in[8];
    const float* x_g     = (const float*)d_in[9];
    const float* W_r     = (const float*)d_in[10];
    const float* W_k     = (const float*)d_in[11];
    const float* W_v     = (const float*)d_in[12];
    const float* W_o     = (const float*)d_in[13];
    const float* w0      = (const float*)d_in[14];
    const float* w1      = (const float*)d_in[15];
    const float* w2      = (const float*)d_in[16];
    const float* a0      = (const float*)d_in[17];
    const float* a1      = (const float*)d_in[18];
    const float* a2      = (const float*)d_in[19];
    const float* v0      = (const float*)d_in[20];
    const float* v1      = (const float*)d_in[21];
    const float* v2      = (const float*)d_in[22];
    const float* g1      = (const float*)d_in[23];
    const float* g2      = (const float*)d_in[24];
    const float* k_k     = (const float*)d_in[25];
    const float* k_a     = (const float*)d_in[26];
    const float* r_k     = (const float*)d_in[27];
    const float* ln_x_w  = (const float*)d_in[28];
    const float* ln_x_b  = (const float*)d_in[29];
    const float* ln1_w   = (const float*)d_in[30];
    const float* ln1_b   = (const float*)d_in[31];

    float* sc = nullptr;
    cudaGetSymbolAddress((void**)&sc, d_scratch);
    __nv_bfloat16* bf = (__nv_bfloat16*)(sc + OFS_BF16);

    float* p_xn   = sc + OFS_XN;
    float* p_xw   = sc + OFS_XW;
    float* p_xv   = sc + OFS_XV;
    float* p_xa   = sc + OFS_XA;
    float* p_xg   = sc + OFS_XG;
    float* p_r    = sc + OFS_R;
    float* p_k    = sc + OFS_K;
    float* p_v    = sc + OFS_V;
    float* p_g    = sc + OFS_G;
    float* p_a    = sc + OFS_A;
    float* p_wd   = sc + OFS_WD;
    float* p_vm   = sc + OFS_VM;
    float* p_y    = sc + OFS_Y;
    float* p_gt   = sc + OFS_GT;
    float* p_at   = sc + OFS_AT;
    float* p_wt   = sc + OFS_WT;
    float* p_vt   = sc + OFS_VT;
    float* p_pt   = sc + OFS_PART;
    float* p_s2m  = sc + OFS_S2M;
    float* p_pk   = sc + OFS_PK;

    float* out = (float*)d_out;
    const size_t nMain = TH;
    const size_t nS1   = H_DIM;
    const size_t nS2   = (size_t)NHEAD * HSZ * HSZ;
    float* o_s1 = ((size_t)out_size >= nMain + nS1)            ? out + nMain             : nullptr;
    float* o_s2 = ((size_t)out_size >= nMain + nS1 + nS2)      ? out + nMain + nS1       : nullptr;
    float* o_vf = ((size_t)out_size >= nMain + nS1 + nS2 + TH) ? out + nMain + nS1 + nS2 : nullptr;

    static cudaStream_t s2s = nullptr;
    static cudaEvent_t eF = nullptr, eC = nullptr, eC2 = nullptr, eM = nullptr,
                       eS = nullptr, eG = nullptr, e1 = nullptr, eJ = nullptr;
    if (s2s == nullptr) {
        cudaStreamCreateWithFlags(&s2s, cudaStreamNonBlocking);
        cudaEventCreateWithFlags(&eF, cudaEventDisableTiming);
        cudaEventCreateWithFlags(&eC, cudaEventDisableTiming);
        cudaEventCreateWithFlags(&eC2, cudaEventDisableTiming);
        cudaEventCreateWithFlags(&eM, cudaEventDisableTiming);
        cudaEventCreateWithFlags(&eS, cudaEventDisableTiming);
        cudaEventCreateWithFlags(&eG, cudaEventDisableTiming);
        cudaEventCreateWithFlags(&e1, cudaEventDisableTiming);
        cudaEventCreateWithFlags(&eJ, cudaEventDisableTiming);
        cudaFuncSetAttribute(mma_gemm_kernel, cudaFuncAttributeMaxDynamicSharedMemorySize, GEMM_SMEM);
    }

    // ---- fork side stream ----
    cudaEventRecord(eF, 0);
    cudaStreamWaitEvent(s2s, eF, 0);

    // side: W_r/W_k/W_v cvt (gates front GEMM), then W_o cvt + v_first copy
    cvt3_kernel<<<dim3(4096, 3), 256, 0, s2s>>>(W_r, W_k, W_v, bf);
    cudaEventRecord(eC, s2s);
    cvt_kernel<<<4096, 256, 0, s2s>>>(W_o, bf + BO_WOH, bf + BO_WOL);
    if (o_vf != nullptr) copy_kernel<<<4096, 512, 0, s2s>>>(v_first, o_vf, TH);
    cudaEventRecord(eC2, s2s);

    // main: LN + mix
    ln1_kernel<<<T_LEN, 256>>>(x, ln1_w, ln1_b, p_xn, o_s1);
    mix_kernel<<<4096, 512>>>(p_xn, state1, x_r, x_w, x_k, x_v, x_a, x_g,
                              bf + BO_XRH, bf + BO_XRL, bf + BO_XKH, bf + BO_XKL,
                              bf + BO_XVH, bf + BO_XVL, p_xw, p_xv, p_xa, p_xg);
    cudaEventRecord(eM, 0);

    // side: MLP chain (needs mix). a/w/v stage-2 gate prep; g stage-2 gates only post.
    cudaStreamWaitEvent(s2s, eM, 0);
    s1_splitk_kernel<<<dim3(5, 16, 8), 256, 0, s2s>>>(p_xg, p_xa, p_xw, p_xv, g1, a1, w1, v1, p_pt);
    s1_reduce_kernel<<<1024, 288, 0, s2s>>>(p_pt, p_gt, p_at, p_wt, p_vt);
    s2_gemm_kernel<<<dim3(32, 16, 3), 256, 0, s2s>>>(p_gt, p_at, p_wt, p_vt,
                                                     g2, a2, w2, v2, a0, w0, v0,
                                                     p_g, p_a, p_wd, p_vm, 1);
    cudaEventRecord(eS, s2s);
    s2_gemm_kernel<<<dim3(32, 16, 1), 256, 0, s2s>>>(p_gt, p_at, p_wt, p_vt,
                                                     g2, a2, w2, v2, a0, w0, v0,
                                                     p_g, p_a, p_wd, p_vm, 0);
    cudaEventRecord(eG, s2s);

    // main: fused 3-GEMM launch (needs cvt3 + mix)
    cudaStreamWaitEvent(0, eC, 0);
    {
        GemmArgs ga;
        ga.Ah[0] = bf + BO_XRH; ga.Al[0] = bf + BO_XRL; ga.Bh[0] = bf + BO_WRH; ga.Bl[0] = bf + BO_WRL;
        ga.Ah[1] = bf + BO_XKH; ga.Al[1] = bf + BO_XKL; ga.Bh[1] = bf + BO_WKH; ga.Bl[1] = bf + BO_WKL;
        ga.Ah[2] = bf + BO_XVH; ga.Al[2] = bf + BO_XVL; ga.Bh[2] = bf + BO_WVH; ga.Bl[2] = bf + BO_WVL;
        ga.C[0] = p_r; ga.C[1] = p_k; ga.C[2] = p_v;
        ga.R[0] = ga.R[1] = ga.R[2] = nullptr;
        ga.m0 = 0;
        mma_gemm_kernel<<<dim3(16, 8, 3), 256, GEMM_SMEM>>>(ga);
    }

    // join a/w/v MLP outputs, then prep
    cudaStreamWaitEvent(0, eS, 0);
    prep_kernel<<<T_LEN * NHEAD / 4, 256>>>(p_k, p_a, p_v, p_vm, v_first, p_r, p_wd, k_k, k_a, p_pk);

    // scan half 1 (t 0..512), state -> s2mid
    scan_kernel<<<128, 256>>>(p_pk, state2, p_y, p_s2m, 0, 512);
    cudaEventRecord(e1, 0);

    // scan half 2 (t 512..1024), state -> s2 output
    scan_kernel<<<128, 256>>>(p_pk, p_s2m, p_y, o_s2, 512, 1024);

    // side: post + W_o for first half, overlapped with scan half 2
    GemmArgs go;
    go.Ah[0] = bf + BO_OPH; go.Al[0] = bf + BO_OPL; go.Bh[0] = bf + BO_WOH; go.Bl[0] = bf + BO_WOL;
    go.Ah[1] = go.Ah[0]; go.Al[1] = go.Al[0]; go.Bh[1] = go.Bh[0]; go.Bl[1] = go.Bl[0];
    go.Ah[2] = go.Ah[0]; go.Al[2] = go.Al[0]; go.Bh[2] = go.Bh[0]; go.Bl[2] = go.Bl[0];
    go.C[0] = out; go.C[1] = out; go.C[2] = out;
    go.R[0] = x; go.R[1] = x; go.R[2] = x;

    cudaStreamWaitEvent(s2s, e1, 0);
    cudaStreamWaitEvent(s2s, eG, 0);
    post_kernel<<<512 * NHEAD, 64, 0, s2s>>>(p_y, p_pk, p_g, r_k, ln_x_w, ln_x_b,
                                             bf + BO_OPH, bf + BO_OPL, 0);
    cudaStreamWaitEvent(s2s, eC2, 0);
    {
        GemmArgs g0 = go; g0.m0 = 0;
        mma_gemm_kernel<<<dim3(16, 4, 1), 256, GEMM_SMEM, s2s>>>(g0);
    }
    cudaEventRecord(eJ, s2s);

    // main: post + W_o for second half
    cudaStreamWaitEvent(0, eG, 0);
    post_kernel<<<512 * NHEAD, 64>>>(p_y, p_pk, p_g, r_k, ln_x_w, ln_x_b,
                                     bf + BO_OPH, bf + BO_OPL, 512);
    cudaStreamWaitEvent(0, eC2, 0);
    {
        GemmArgs g1a = go; g1a.m0 = 512;
        mma_gemm_kernel<<<dim3(16, 4, 1), 256, GEMM_SMEM>>>(g1a);
    }

    // join side stream back into origin for capture completeness
    cudaStreamWaitEvent(0, eJ, 0);
}